// round 1
// baseline (speedup 1.0000x reference)
#include <cuda_runtime.h>

#define NN   50000
#define EE   1600000
#define FIN  512
#define F1   64        // H1*C1
#define NH1  8
#define C2   40
#define FULLM 0xffffffffu

// ------------------------- scratch (static device memory; no allocs allowed)
__device__ float g_h1[NN * F1];        // layer1 linear output  [N,8,8]
__device__ float g_as1[NN * NH1];      // alpha_src layer1      [N,8]
__device__ float g_ad1[NN * NH1];      // alpha_dst layer1      [N,8]
__device__ float g_x2[NN * F1];        // relu(layer1 out)      [N,64]
__device__ float g_h2[NN * C2];        // layer2 linear output  [N,40]
__device__ float g_as2[NN];
__device__ float g_ad2[NN];
__device__ int   g_deg[NN];
__device__ int   g_rowptr[NN + 1];
__device__ int   g_cursor[NN];
__device__ int   g_col[EE];            // src node per CSR slot (sorted by dst)

// ------------------------- GEMM1: g_h1 = x @ W1   (N x 512) @ (512 x 64)
__global__ __launch_bounds__(256) void k_gemm1(const float* __restrict__ x,
                                               const float* __restrict__ W1) {
    __shared__ float As[32][68];   // [k][m], padded
    __shared__ float Bs[32][68];   // [k][n], padded (row stride 272B, 16B-aligned)
    const int m0 = blockIdx.x * 64;
    const int t  = threadIdx.x;
    const int tx = t & 15, ty = t >> 4;

    float acc[4][4];
#pragma unroll
    for (int i = 0; i < 4; i++)
#pragma unroll
        for (int j = 0; j < 4; j++) acc[i][j] = 0.f;

    const int am = t >> 2;          // 0..63
    const int ak = (t & 3) * 8;     // 0,8,16,24
    const int bk = t >> 3;          // 0..31
    const int bn = (t & 7) * 8;     // 0..56
    const int gm = m0 + am;

    for (int kc = 0; kc < FIN; kc += 32) {
        float4 a0, a1;
        if (gm < NN) {
            a0 = *(const float4*)&x[gm * FIN + kc + ak];
            a1 = *(const float4*)&x[gm * FIN + kc + ak + 4];
        } else {
            a0 = make_float4(0.f, 0.f, 0.f, 0.f);
            a1 = a0;
        }
        As[ak + 0][am] = a0.x; As[ak + 1][am] = a0.y;
        As[ak + 2][am] = a0.z; As[ak + 3][am] = a0.w;
        As[ak + 4][am] = a1.x; As[ak + 5][am] = a1.y;
        As[ak + 6][am] = a1.z; As[ak + 7][am] = a1.w;

        float4 b0 = *(const float4*)&W1[(kc + bk) * F1 + bn];
        float4 b1 = *(const float4*)&W1[(kc + bk) * F1 + bn + 4];
        *(float4*)&Bs[bk][bn]     = b0;
        *(float4*)&Bs[bk][bn + 4] = b1;
        __syncthreads();

#pragma unroll
        for (int k = 0; k < 32; k++) {
            float4 a = *(const float4*)&As[k][ty * 4];
            float4 b = *(const float4*)&Bs[k][tx * 4];
            acc[0][0] += a.x * b.x; acc[0][1] += a.x * b.y; acc[0][2] += a.x * b.z; acc[0][3] += a.x * b.w;
            acc[1][0] += a.y * b.x; acc[1][1] += a.y * b.y; acc[1][2] += a.y * b.z; acc[1][3] += a.y * b.w;
            acc[2][0] += a.z * b.x; acc[2][1] += a.z * b.y; acc[2][2] += a.z * b.z; acc[2][3] += a.z * b.w;
            acc[3][0] += a.w * b.x; acc[3][1] += a.w * b.y; acc[3][2] += a.w * b.z; acc[3][3] += a.w * b.w;
        }
        __syncthreads();
    }
#pragma unroll
    for (int i = 0; i < 4; i++) {
        int r = m0 + ty * 4 + i;
        if (r < NN)
            *(float4*)&g_h1[r * F1 + tx * 4] =
                make_float4(acc[i][0], acc[i][1], acc[i][2], acc[i][3]);
    }
}

// ------------------------- per-node attention coefficients, layer 1
__global__ void k_att1(const float* __restrict__ att_s, const float* __restrict__ att_d) {
    int idx = blockIdx.x * blockDim.x + threadIdx.x;   // n*8 + h
    if (idx >= NN * NH1) return;
    int h = idx & 7;
    const float* hp = &g_h1[idx * 8];
    float4 h0 = *(const float4*)hp;
    float4 h1 = *(const float4*)(hp + 4);
    float4 s0 = *(const float4*)&att_s[h * 8];
    float4 s1 = *(const float4*)&att_s[h * 8 + 4];
    float4 d0 = *(const float4*)&att_d[h * 8];
    float4 d1 = *(const float4*)&att_d[h * 8 + 4];
    g_as1[idx] = h0.x*s0.x + h0.y*s0.y + h0.z*s0.z + h0.w*s0.w
               + h1.x*s1.x + h1.y*s1.y + h1.z*s1.z + h1.w*s1.w;
    g_ad1[idx] = h0.x*d0.x + h0.y*d0.y + h0.z*d0.z + h0.w*d0.w
               + h1.x*d1.x + h1.y*d1.y + h1.z*d1.z + h1.w*d1.w;
}

// ------------------------- CSR build
__global__ void k_zero() {
    int i = blockIdx.x * blockDim.x + threadIdx.x;
    if (i < NN) g_deg[i] = 0;
}
__global__ void k_hist(const int* __restrict__ dst) {
    int e = blockIdx.x * blockDim.x + threadIdx.x;
    if (e < EE) atomicAdd(&g_deg[dst[e]], 1);
}
__global__ __launch_bounds__(1024) void k_scan() {
    const int T = 1024;
    int t = threadIdx.x;
    int chunk = (NN + T - 1) / T;
    int b = t * chunk;
    int e = min(b + chunk, NN);
    int s = 0;
    for (int i = b; i < e; i++) s += g_deg[i];
    __shared__ int ps[T];
    ps[t] = s;
    __syncthreads();
    for (int off = 1; off < T; off <<= 1) {
        int v = (t >= off) ? ps[t - off] : 0;
        __syncthreads();
        ps[t] += v;
        __syncthreads();
    }
    int run = (t == 0) ? 0 : ps[t - 1];
    for (int i = b; i < e; i++) {
        g_rowptr[i] = run;
        g_cursor[i] = run;
        run += g_deg[i];
    }
    if (t == T - 1) g_rowptr[NN] = run;
}
__global__ void k_scatter(const int* __restrict__ src, const int* __restrict__ dst) {
    int e = blockIdx.x * blockDim.x + threadIdx.x;
    if (e < EE) {
        int d = dst[e];
        int p = atomicAdd(&g_cursor[d], 1);
        g_col[p] = src[e];
    }
}

// ------------------------- layer-1 softmax aggregation, one warp per dst node
__global__ __launch_bounds__(256) void k_agg1(const float* __restrict__ b1) {
    int wid  = (blockIdx.x * 256 + threadIdx.x) >> 5;
    int lane = threadIdx.x & 31;
    if (wid >= NN) return;
    const int i   = wid;
    const int beg = g_rowptr[i];
    const int deg = g_rowptr[i + 1] - beg;
    const int total = deg + 1;                 // + self loop

    float4 ad0 = *(const float4*)&g_ad1[i * 8];
    float4 ad1 = *(const float4*)&g_ad1[i * 8 + 4];
    float adr[8] = { ad0.x, ad0.y, ad0.z, ad0.w, ad1.x, ad1.y, ad1.z, ad1.w };

    float m[8], s[8];
#pragma unroll
    for (int h = 0; h < 8; h++) { m[h] = -1e30f; s[h] = 0.f; }

    // pass 1: online softmax stats per head (lane-per-edge)
    for (int k = lane; k < total; k += 32) {
        int srcn = (k < deg) ? g_col[beg + k] : i;
        float4 s0 = *(const float4*)&g_as1[srcn * 8];
        float4 s1 = *(const float4*)&g_as1[srcn * 8 + 4];
        float lg[8] = { s0.x + adr[0], s0.y + adr[1], s0.z + adr[2], s0.w + adr[3],
                        s1.x + adr[4], s1.y + adr[5], s1.z + adr[6], s1.w + adr[7] };
#pragma unroll
        for (int h = 0; h < 8; h++) {
            float l = lg[h];
            l = l > 0.f ? l : 0.2f * l;
            if (l <= m[h]) {
                s[h] += __expf(l - m[h]);
            } else {
                s[h] = s[h] * __expf(m[h] - l) + 1.0f;
                m[h] = l;
            }
        }
    }
    // warp combine (max, sum) per head
#pragma unroll
    for (int h = 0; h < 8; h++) {
#pragma unroll
        for (int off = 16; off > 0; off >>= 1) {
            float mo = __shfl_xor_sync(FULLM, m[h], off);
            float so = __shfl_xor_sync(FULLM, s[h], off);
            float M  = fmaxf(m[h], mo);
            s[h] = s[h] * __expf(m[h] - M) + so * __expf(mo - M);
            m[h] = M;
        }
    }

    // this lane owns channels 2*lane, 2*lane+1 -> head = lane>>2
    const int hl = lane >> 2;
    float myM = 0.f, myS = 1.f, myAd = 0.f;
#pragma unroll
    for (int h = 0; h < 8; h++)
        if (hl == h) { myM = m[h]; myS = s[h]; myAd = adr[h]; }
    float myInv = __fdividef(1.0f, myS);

    // pass 2: cooperative weighted gather of h1[src] rows
    float accx = 0.f, accy = 0.f;
    for (int k0 = 0; k0 < total; k0 += 32) {
        int kk = k0 + lane;
        int my_src = (kk < deg) ? g_col[beg + kk] : i;
        int lim = min(32, total - k0);
        for (int j = 0; j < lim; j++) {
            int srcn = __shfl_sync(FULLM, my_src, j);
            float l = g_as1[srcn * 8 + hl] + myAd;
            l = l > 0.f ? l : 0.2f * l;
            float w = __expf(l - myM) * myInv;
            float2 hv = *(const float2*)&g_h1[srcn * F1 + lane * 2];
            accx += w * hv.x;
            accy += w * hv.y;
        }
    }
    int c0 = lane * 2;
    g_x2[i * F1 + c0]     = fmaxf(accx + b1[c0], 0.f);
    g_x2[i * F1 + c0 + 1] = fmaxf(accy + b1[c0 + 1], 0.f);
}

// ------------------------- layer-2 linear + attention coefficients (warp/node)
__global__ __launch_bounds__(256) void k_gemm2(const float* __restrict__ W2,
                                               const float* __restrict__ att_s,
                                               const float* __restrict__ att_d) {
    __shared__ float sW[F1 * C2];
    __shared__ float sAs[C2], sAd[C2];
    for (int idx = threadIdx.x; idx < F1 * C2; idx += 256) sW[idx] = W2[idx];
    if (threadIdx.x < C2) {
        sAs[threadIdx.x] = att_s[threadIdx.x];
        sAd[threadIdx.x] = att_d[threadIdx.x];
    }
    __syncthreads();

    int wid  = (blockIdx.x * 256 + threadIdx.x) >> 5;
    int lane = threadIdx.x & 31;
    if (wid >= NN) return;
    const int n  = wid;
    const int c0 = lane;
    const int c1 = lane + 32;
    const bool has1 = (c1 < C2);

    float acc0 = 0.f, acc1 = 0.f;
#pragma unroll 8
    for (int k = 0; k < F1; k++) {
        float xv = g_x2[n * F1 + k];      // broadcast across warp
        acc0 += xv * sW[k * C2 + c0];
        if (has1) acc1 += xv * sW[k * C2 + c1];
    }
    g_h2[n * C2 + c0] = acc0;
    if (has1) g_h2[n * C2 + c1] = acc1;

    float ps = acc0 * sAs[c0] + (has1 ? acc1 * sAs[c1] : 0.f);
    float pd = acc0 * sAd[c0] + (has1 ? acc1 * sAd[c1] : 0.f);
#pragma unroll
    for (int off = 16; off > 0; off >>= 1) {
        ps += __shfl_xor_sync(FULLM, ps, off);
        pd += __shfl_xor_sync(FULLM, pd, off);
    }
    if (lane == 0) { g_as2[n] = ps; g_ad2[n] = pd; }
}

// ------------------------- layer-2 aggregation + bias + log_softmax (warp/node)
__global__ __launch_bounds__(256) void k_agg2(const float* __restrict__ b2,
                                              float* __restrict__ out) {
    int wid  = (blockIdx.x * 256 + threadIdx.x) >> 5;
    int lane = threadIdx.x & 31;
    if (wid >= NN) return;
    const int n   = wid;
    const int beg = g_rowptr[n];
    const int deg = g_rowptr[n + 1] - beg;
    const int total = deg + 1;
    const float adn = g_ad2[n];

    float m = -1e30f, s = 0.f;
    for (int k = lane; k < total; k += 32) {
        int srcn = (k < deg) ? g_col[beg + k] : n;
        float l = g_as2[srcn] + adn;
        l = l > 0.f ? l : 0.2f * l;
        if (l <= m) {
            s += __expf(l - m);
        } else {
            s = s * __expf(m - l) + 1.0f;
            m = l;
        }
    }
#pragma unroll
    for (int off = 16; off > 0; off >>= 1) {
        float mo = __shfl_xor_sync(FULLM, m, off);
        float so = __shfl_xor_sync(FULLM, s, off);
        float M  = fmaxf(m, mo);
        s = s * __expf(m - M) + so * __expf(mo - M);
        m = M;
    }
    float inv = __fdividef(1.0f, s);

    const int c0 = lane;
    const int c1 = lane + 32;
    const bool has1 = (c1 < C2);
    float acc0 = 0.f, acc1 = 0.f;
    for (int k0 = 0; k0 < total; k0 += 32) {
        int kk = k0 + lane;
        int my_src = (kk < deg) ? g_col[beg + kk] : n;
        int lim = min(32, total - k0);
        for (int j = 0; j < lim; j++) {
            int srcn = __shfl_sync(FULLM, my_src, j);
            float l = g_as2[srcn] + adn;
            l = l > 0.f ? l : 0.2f * l;
            float w = __expf(l - m) * inv;
            acc0 += w * g_h2[srcn * C2 + c0];
            if (has1) acc1 += w * g_h2[srcn * C2 + c1];
        }
    }
    float o0 = acc0 + b2[c0];
    float o1 = has1 ? (acc1 + b2[c1]) : -1e30f;

    // fused log_softmax over the 40 logits held in this warp
    float mx = fmaxf(o0, o1);
#pragma unroll
    for (int off = 16; off > 0; off >>= 1)
        mx = fmaxf(mx, __shfl_xor_sync(FULLM, mx, off));
    float se = __expf(o0 - mx) + (has1 ? __expf(o1 - mx) : 0.f);
#pragma unroll
    for (int off = 16; off > 0; off >>= 1)
        se += __shfl_xor_sync(FULLM, se, off);
    float lse = mx + __logf(se);

    out[n * C2 + c0] = o0 - lse;
    if (has1) out[n * C2 + c1] = o1 - lse;
}

// ------------------------- launch
extern "C" void kernel_launch(void* const* d_in, const int* in_sizes, int n_in,
                              void* d_out, int out_size) {
    const float* x        = (const float*)d_in[0];
    const int*   ei       = (const int*)d_in[1];
    const float* W1       = (const float*)d_in[2];
    const float* att_src1 = (const float*)d_in[3];
    const float* att_dst1 = (const float*)d_in[4];
    const float* b1       = (const float*)d_in[5];
    const float* W2       = (const float*)d_in[6];
    const float* att_src2 = (const float*)d_in[7];
    const float* att_dst2 = (const float*)d_in[8];
    const float* b2       = (const float*)d_in[9];
    float* out = (float*)d_out;

    const int* src = ei;
    const int* dst = ei + EE;

    // CSR build
    k_zero<<<(NN + 255) / 256, 256>>>();
    k_hist<<<(EE + 255) / 256, 256>>>(dst);
    k_scan<<<1, 1024>>>();
    k_scatter<<<(EE + 255) / 256, 256>>>(src, dst);

    // layer 1
    k_gemm1<<<(NN + 63) / 64, 256>>>(x, W1);
    k_att1<<<(NN * NH1 + 255) / 256, 256>>>(att_src1, att_dst1);
    k_agg1<<<(NN + 7) / 8, 256>>>(b1);

    // layer 2 + log_softmax
    k_gemm2<<<(NN + 7) / 8, 256>>>(W2, att_src2, att_dst2);
    k_agg2<<<(NN + 7) / 8, 256>>>(b2, out);
}

// round 2
// speedup vs baseline: 1.5048x; 1.5048x over previous
#include <cuda_runtime.h>

#define NN   50000
#define EE   1600000
#define FIN  512
#define F1   64        // H1*C1
#define NH1  8
#define C2   40
#define NBLK 196       // ceil(NN/256)
#define FULLM 0xffffffffu

// ------------------------- scratch (static device memory; no allocs allowed)
__device__ float g_h1[NN * F1];
__device__ float g_as1[NN * NH1];
__device__ float g_ad1[NN * NH1];
__device__ float g_x2[NN * F1];
__device__ float g_h2[NN * C2];
__device__ float g_as2[NN];
__device__ float g_ad2[NN];
__device__ int   g_deg[NN];
__device__ int   g_rowloc[NN];
__device__ int   g_bsum[256];
__device__ int   g_boff[256];
__device__ int   g_rowptr[NN + 1];
__device__ int   g_cursor[NN];
__device__ int   g_col[EE];

__device__ __forceinline__ float leaky(float v) { return v > 0.f ? v : 0.2f * v; }

// ------------------------- GEMM1 + fused attention coeffs
__global__ __launch_bounds__(128) void k_gemm1(const float* __restrict__ x,
                                               const float* __restrict__ W1,
                                               const float* __restrict__ attS,
                                               const float* __restrict__ attD) {
    __shared__ float As[32][132];
    __shared__ float Bs[32][72];
    __shared__ float sAs[64], sAd[64];
    const int t  = threadIdx.x;
    const int tx = t & 7;
    const int ty = t >> 3;
    const int m0 = blockIdx.x * 128;
    if (t < 64) { sAs[t] = attS[t]; sAd[t] = attD[t]; }

    float acc[8][8];
#pragma unroll
    for (int i = 0; i < 8; i++)
#pragma unroll
        for (int j = 0; j < 8; j++) acc[i][j] = 0.f;

    const int gm    = m0 + t;
    const bool aval = gm < NN;
    const float* xrow = x + (long)gm * FIN;

    for (int kc = 0; kc < FIN; kc += 32) {
        float4 a[8];
        if (aval) {
#pragma unroll
            for (int i = 0; i < 8; i++)
                a[i] = *(const float4*)&xrow[kc + i * 4];
        } else {
#pragma unroll
            for (int i = 0; i < 8; i++) a[i] = make_float4(0.f, 0.f, 0.f, 0.f);
        }
#pragma unroll
        for (int i = 0; i < 8; i++) {
            As[i * 4 + 0][t] = a[i].x;
            As[i * 4 + 1][t] = a[i].y;
            As[i * 4 + 2][t] = a[i].z;
            As[i * 4 + 3][t] = a[i].w;
        }
#pragma unroll
        for (int i = 0; i < 4; i++) {
            int f   = t + i * 128;
            int row = f >> 4;
            int c4  = (f & 15) * 4;
            *(float4*)&Bs[row][c4] = *(const float4*)&W1[(kc + row) * F1 + c4];
        }
        __syncthreads();

#pragma unroll 8
        for (int k = 0; k < 32; k++) {
            float4 a0 = *(const float4*)&As[k][ty * 8];
            float4 a1 = *(const float4*)&As[k][ty * 8 + 4];
            float4 b0 = *(const float4*)&Bs[k][tx * 8];
            float4 b1 = *(const float4*)&Bs[k][tx * 8 + 4];
            float av[8] = { a0.x, a0.y, a0.z, a0.w, a1.x, a1.y, a1.z, a1.w };
            float bv[8] = { b0.x, b0.y, b0.z, b0.w, b1.x, b1.y, b1.z, b1.w };
#pragma unroll
            for (int i = 0; i < 8; i++)
#pragma unroll
                for (int j = 0; j < 8; j++)
                    acc[i][j] += av[i] * bv[j];
        }
        __syncthreads();
    }

#pragma unroll
    for (int i = 0; i < 8; i++) {
        int r = m0 + ty * 8 + i;
        if (r >= NN) break;
        *(float4*)&g_h1[r * F1 + tx * 8] =
            make_float4(acc[i][0], acc[i][1], acc[i][2], acc[i][3]);
        *(float4*)&g_h1[r * F1 + tx * 8 + 4] =
            make_float4(acc[i][4], acc[i][5], acc[i][6], acc[i][7]);
        float ps = 0.f, pd = 0.f;
#pragma unroll
        for (int j = 0; j < 8; j++) {
            ps += acc[i][j] * sAs[tx * 8 + j];
            pd += acc[i][j] * sAd[tx * 8 + j];
        }
        g_as1[r * NH1 + tx] = ps;
        g_ad1[r * NH1 + tx] = pd;
    }
}

// ------------------------- CSR build
__global__ void k_zero() {
    int i = blockIdx.x * blockDim.x + threadIdx.x;
    if (i < NN) g_deg[i] = 0;
}
__global__ void k_hist(const int* __restrict__ dst) {
    int e = blockIdx.x * blockDim.x + threadIdx.x;
    if (e < EE) atomicAdd(&g_deg[dst[e]], 1);
}
__global__ __launch_bounds__(256) void k_part() {
    __shared__ int sm[256];
    int t = threadIdx.x, i = blockIdx.x * 256 + t;
    int d = (i < NN) ? g_deg[i] : 0;
    sm[t] = d;
    __syncthreads();
#pragma unroll
    for (int off = 1; off < 256; off <<= 1) {
        int v = (t >= off) ? sm[t - off] : 0;
        __syncthreads();
        sm[t] += v;
        __syncthreads();
    }
    if (i < NN) g_rowloc[i] = sm[t] - d;
    if (t == 255) g_bsum[blockIdx.x] = sm[255];
}
__global__ __launch_bounds__(256) void k_bscan() {
    __shared__ int sm[256];
    int t = threadIdx.x;
    int d = (t < NBLK) ? g_bsum[t] : 0;
    sm[t] = d;
    __syncthreads();
#pragma unroll
    for (int off = 1; off < 256; off <<= 1) {
        int v = (t >= off) ? sm[t - off] : 0;
        __syncthreads();
        sm[t] += v;
        __syncthreads();
    }
    if (t < NBLK) g_boff[t] = sm[t] - d;
    if (t == NBLK - 1) g_rowptr[NN] = sm[t];
}
__global__ void k_fix() {
    int i = blockIdx.x * blockDim.x + threadIdx.x;
    if (i < NN) {
        int rp = g_rowloc[i] + g_boff[blockIdx.x];
        g_rowptr[i] = rp;
        g_cursor[i] = rp;
    }
}
__global__ void k_scatter(const int* __restrict__ src, const int* __restrict__ dst) {
    int e = blockIdx.x * blockDim.x + threadIdx.x;
    if (e < EE) {
        int d = dst[e];
        int p = atomicAdd(&g_cursor[d], 1);
        g_col[p] = src[e];
    }
}

// ------------------------- layer-1 softmax aggregation, one warp per dst node
__global__ __launch_bounds__(256) void k_agg1(const float* __restrict__ b1) {
    __shared__ float sw[8][8][36];
    __shared__ int   ssrc[8][32];
    const int w    = threadIdx.x >> 5;
    const int lane = threadIdx.x & 31;
    const int node = blockIdx.x * 8 + w;
    if (node >= NN) return;
    const int beg   = g_rowptr[node];
    const int deg   = g_rowptr[node + 1] - beg;
    const int total = deg + 1;

    float4 ad0 = *(const float4*)&g_ad1[node * 8];
    float4 ad1 = *(const float4*)&g_ad1[node * 8 + 4];
    float adr[8] = { ad0.x, ad0.y, ad0.z, ad0.w, ad1.x, ad1.y, ad1.z, ad1.w };

    float m[8];
#pragma unroll
    for (int h = 0; h < 8; h++) m[h] = -1e30f;
    for (int k = lane; k < total; k += 32) {
        int srcn = (k < deg) ? g_col[beg + k] : node;
        float4 s0 = *(const float4*)&g_as1[srcn * 8];
        float4 s1 = *(const float4*)&g_as1[srcn * 8 + 4];
        float lg[8] = { s0.x + adr[0], s0.y + adr[1], s0.z + adr[2], s0.w + adr[3],
                        s1.x + adr[4], s1.y + adr[5], s1.z + adr[6], s1.w + adr[7] };
#pragma unroll
        for (int h = 0; h < 8; h++) m[h] = fmaxf(m[h], leaky(lg[h]));
    }
#pragma unroll
    for (int h = 0; h < 8; h++) {
#pragma unroll
        for (int off = 16; off > 0; off >>= 1)
            m[h] = fmaxf(m[h], __shfl_xor_sync(FULLM, m[h], off));
    }

    const int hl = lane >> 2;
    const int c0 = lane * 2;
    float acc0 = 0.f, acc1 = 0.f;
    float ssum[8];
#pragma unroll
    for (int h = 0; h < 8; h++) ssum[h] = 0.f;

    for (int k0 = 0; k0 < total; k0 += 32) {
        int kk  = k0 + lane;
        int lim = min(32, total - k0);
        __syncwarp();
        if (kk < total) {
            int srcn = (kk < deg) ? g_col[beg + kk] : node;
            float4 s0 = *(const float4*)&g_as1[srcn * 8];
            float4 s1 = *(const float4*)&g_as1[srcn * 8 + 4];
            float lg[8] = { s0.x + adr[0], s0.y + adr[1], s0.z + adr[2], s0.w + adr[3],
                            s1.x + adr[4], s1.y + adr[5], s1.z + adr[6], s1.w + adr[7] };
#pragma unroll
            for (int h = 0; h < 8; h++) {
                float wt = __expf(leaky(lg[h]) - m[h]);
                ssum[h] += wt;
                sw[w][h][lane] = wt;
            }
            ssrc[w][lane] = srcn;
        }
        __syncwarp();
        for (int j = 0; j < lim; j++) {
            int srcn = ssrc[w][j];
            float wt = sw[w][hl][j];
            float2 hv = *(const float2*)&g_h1[srcn * F1 + c0];
            acc0 += wt * hv.x;
            acc1 += wt * hv.y;
        }
    }
#pragma unroll
    for (int h = 0; h < 8; h++) {
#pragma unroll
        for (int off = 16; off > 0; off >>= 1)
            ssum[h] += __shfl_xor_sync(FULLM, ssum[h], off);
    }
    float myS = 0.f;
#pragma unroll
    for (int h = 0; h < 8; h++)
        if (hl == h) myS = ssum[h];
    float inv = __fdividef(1.0f, myS);
    g_x2[node * F1 + c0]     = fmaxf(acc0 * inv + b1[c0], 0.f);
    g_x2[node * F1 + c0 + 1] = fmaxf(acc1 * inv + b1[c0 + 1], 0.f);
}

// ------------------------- layer-2 linear + attention coefficients (warp/node)
__global__ __launch_bounds__(256) void k_gemm2(const float* __restrict__ W2,
                                               const float* __restrict__ att_s,
                                               const float* __restrict__ att_d) {
    __shared__ float sW[F1 * C2];
    __shared__ float sAs[C2], sAd[C2];
    for (int idx = threadIdx.x; idx < F1 * C2; idx += 256) sW[idx] = W2[idx];
    if (threadIdx.x < C2) {
        sAs[threadIdx.x] = att_s[threadIdx.x];
        sAd[threadIdx.x] = att_d[threadIdx.x];
    }
    __syncthreads();

    int wid  = (blockIdx.x * 256 + threadIdx.x) >> 5;
    int lane = threadIdx.x & 31;
    if (wid >= NN) return;
    const int n  = wid;
    const int c0 = lane;
    const int c1 = lane + 32;
    const bool has1 = (c1 < C2);

    float2 v = *(const float2*)&g_x2[n * F1 + lane * 2];
    float acc0 = 0.f, acc1 = 0.f;
#pragma unroll
    for (int kk = 0; kk < 32; kk++) {
        float x0 = __shfl_sync(FULLM, v.x, kk);
        float x1 = __shfl_sync(FULLM, v.y, kk);
        acc0 += x0 * sW[(2 * kk) * C2 + c0] + x1 * sW[(2 * kk + 1) * C2 + c0];
        if (has1)
            acc1 += x0 * sW[(2 * kk) * C2 + c1] + x1 * sW[(2 * kk + 1) * C2 + c1];
    }
    g_h2[n * C2 + c0] = acc0;
    if (has1) g_h2[n * C2 + c1] = acc1;

    float ps = acc0 * sAs[c0] + (has1 ? acc1 * sAs[c1] : 0.f);
    float pd = acc0 * sAd[c0] + (has1 ? acc1 * sAd[c1] : 0.f);
#pragma unroll
    for (int off = 16; off > 0; off >>= 1) {
        ps += __shfl_xor_sync(FULLM, ps, off);
        pd += __shfl_xor_sync(FULLM, pd, off);
    }
    if (lane == 0) { g_as2[n] = ps; g_ad2[n] = pd; }
}

// ------------------------- layer-2 aggregation + bias + log_softmax (warp/node)
__global__ __launch_bounds__(256) void k_agg2(const float* __restrict__ b2,
                                              float* __restrict__ out) {
    __shared__ float swt[8][32];
    __shared__ int   ssrc[8][32];
    const int w    = threadIdx.x >> 5;
    const int lane = threadIdx.x & 31;
    const int node = blockIdx.x * 8 + w;
    if (node >= NN) return;
    const int beg   = g_rowptr[node];
    const int deg   = g_rowptr[node + 1] - beg;
    const int total = deg + 1;
    const float adn = g_ad2[node];

    float m = -1e30f;
    for (int k = lane; k < total; k += 32) {
        int srcn = (k < deg) ? g_col[beg + k] : node;
        m = fmaxf(m, leaky(g_as2[srcn] + adn));
    }
#pragma unroll
    for (int off = 16; off > 0; off >>= 1)
        m = fmaxf(m, __shfl_xor_sync(FULLM, m, off));

    const int c0 = lane;
    const int c1 = lane + 32;
    const bool has1 = (c1 < C2);
    float acc0 = 0.f, acc1 = 0.f, ssum = 0.f;
    for (int k0 = 0; k0 < total; k0 += 32) {
        int kk  = k0 + lane;
        int lim = min(32, total - k0);
        __syncwarp();
        if (kk < total) {
            int srcn = (kk < deg) ? g_col[beg + kk] : node;
            float wt = __expf(leaky(g_as2[srcn] + adn) - m);
            ssum += wt;
            swt[w][lane]  = wt;
            ssrc[w][lane] = srcn;
        }
        __syncwarp();
        for (int j = 0; j < lim; j++) {
            int srcn = ssrc[w][j];
            float wt = swt[w][j];
            acc0 += wt * g_h2[srcn * C2 + c0];
            if (has1) acc1 += wt * g_h2[srcn * C2 + c1];
        }
    }
#pragma unroll
    for (int off = 16; off > 0; off >>= 1)
        ssum += __shfl_xor_sync(FULLM, ssum, off);
    float inv = __fdividef(1.0f, ssum);

    float o0 = acc0 * inv + b2[c0];
    float o1 = has1 ? (acc1 * inv + b2[c1]) : -1e30f;

    float mx = fmaxf(o0, o1);
#pragma unroll
    for (int off = 16; off > 0; off >>= 1)
        mx = fmaxf(mx, __shfl_xor_sync(FULLM, mx, off));
    float se = __expf(o0 - mx) + (has1 ? __expf(o1 - mx) : 0.f);
#pragma unroll
    for (int off = 16; off > 0; off >>= 1)
        se += __shfl_xor_sync(FULLM, se, off);
    float lse = mx + __logf(se);

    out[node * C2 + c0] = o0 - lse;
    if (has1) out[node * C2 + c1] = o1 - lse;
}

// ------------------------- launch
extern "C" void kernel_launch(void* const* d_in, const int* in_sizes, int n_in,
                              void* d_out, int out_size) {
    const float* x        = (const float*)d_in[0];
    const int*   ei       = (const int*)d_in[1];
    const float* W1       = (const float*)d_in[2];
    const float* att_src1 = (const float*)d_in[3];
    const float* att_dst1 = (const float*)d_in[4];
    const float* b1       = (const float*)d_in[5];
    const float* W2       = (const float*)d_in[6];
    const float* att_src2 = (const float*)d_in[7];
    const float* att_dst2 = (const float*)d_in[8];
    const float* b2       = (const float*)d_in[9];
    float* out = (float*)d_out;

    const int* src = ei;
    const int* dst = ei + EE;

    // CSR build
    k_zero<<<(NN + 255) / 256, 256>>>();
    k_hist<<<(EE + 255) / 256, 256>>>(dst);
    k_part<<<NBLK, 256>>>();
    k_bscan<<<1, 256>>>();
    k_fix<<<NBLK, 256>>>();
    k_scatter<<<(EE + 255) / 256, 256>>>(src, dst);

    // layer 1
    k_gemm1<<<(NN + 127) / 128, 128>>>(x, W1, att_src1, att_dst1);
    k_agg1<<<(NN + 7) / 8, 256>>>(b1);

    // layer 2 + log_softmax
    k_gemm2<<<(NN + 7) / 8, 256>>>(W2, att_src2, att_dst2);
    k_agg2<<<(NN + 7) / 8, 256>>>(b2, out);
}

// round 4
// speedup vs baseline: 2.0652x; 1.3724x over previous
#include <cuda_runtime.h>
#include <cstdint>

#define NN   50000
#define EE   1600000
#define FIN  512
#define F1   64        // H1*C1
#define NH1  8
#define C2   40
#define NBLK 196       // ceil(NN/256)
#define FULLM 0xffffffffu

// ------------------------- scratch (static device memory; no allocs allowed)
__device__ float g_h1[NN * F1];
__device__ float g_as1[NN * NH1];
__device__ float g_ad1[NN * NH1];
__device__ float g_h2[NN * C2];
__device__ float g_as2[NN];
__device__ float g_ad2[NN];
__device__ int   g_deg[NN];
__device__ int   g_rowloc[NN];
__device__ int   g_bsum[256];
__device__ int   g_boff[256];
__device__ int   g_rowptr[NN + 1];
__device__ int   g_cursor[NN];
__device__ int   g_col[EE];

__device__ __forceinline__ float leaky(float v) { return v > 0.f ? v : 0.2f * v; }

__device__ __forceinline__ uint32_t f2tf(float f) {
    uint32_t u;
    asm("cvt.rna.tf32.f32 %0, %1;" : "=r"(u) : "f"(f));
    return u;
}

__device__ __forceinline__ void mma_tf32(float* d, const uint32_t* a, const uint32_t* b) {
    asm volatile(
        "mma.sync.aligned.m16n8k8.row.col.f32.tf32.tf32.f32 "
        "{%0,%1,%2,%3}, {%4,%5,%6,%7}, {%8,%9}, {%0,%1,%2,%3};"
        : "+f"(d[0]), "+f"(d[1]), "+f"(d[2]), "+f"(d[3])
        : "r"(a[0]), "r"(a[1]), "r"(a[2]), "r"(a[3]), "r"(b[0]), "r"(b[1]));
}

// ------------------------- GEMM1 (tf32 tensor cores) + fused attention coeffs
// C[128 x 64] per block; 8 warps in 4(M) x 2(N); warp tile 32x32 (m16n8k8)
__global__ __launch_bounds__(256) void k_gemm1(const float* __restrict__ x,
                                               const float* __restrict__ W1,
                                               const float* __restrict__ attS,
                                               const float* __restrict__ attD) {
    __shared__ float sA[128][36];   // [m][k], pad 4 -> frag banks conflict-free
    __shared__ float sB[32][72];    // [k][n], pad 8 -> frag banks conflict-free
    __shared__ float sAs[64], sAd[64];

    const int t    = threadIdx.x;
    const int wid  = t >> 5;
    const int lane = t & 31;
    const int m0   = blockIdx.x * 128;
    const int warp_m = (wid >> 1) * 32;
    const int warp_n = (wid & 1) * 32;
    if (t < 64) { sAs[t] = attS[t]; sAd[t] = attD[t]; }

    float acc[2][4][4];
#pragma unroll
    for (int mi = 0; mi < 2; mi++)
#pragma unroll
        for (int ni = 0; ni < 4; ni++)
#pragma unroll
            for (int e = 0; e < 4; e++) acc[mi][ni][e] = 0.f;

    const int r = lane >> 2;      // 0..7
    const int c = lane & 3;       // 0..3
    const int arow = t >> 3;      // 0..31 (staging: 32 rows/pass)
    const int acol = (t & 7) * 4; // 0..28

    for (int kc = 0; kc < FIN; kc += 32) {
        // stage A: 128x32, 4 passes of 32 rows, coalesced float4 rows
#pragma unroll
        for (int i = 0; i < 4; i++) {
            int row = i * 32 + arow;
            int gm  = m0 + row;
            float4 v = (gm < NN) ? *(const float4*)&x[(long)gm * FIN + kc + acol]
                                 : make_float4(0.f, 0.f, 0.f, 0.f);
            float4 tv;
            tv.x = __uint_as_float(f2tf(v.x));
            tv.y = __uint_as_float(f2tf(v.y));
            tv.z = __uint_as_float(f2tf(v.z));
            tv.w = __uint_as_float(f2tf(v.w));
            *(float4*)&sA[row][acol] = tv;
        }
        // stage B: 32x64, 2 passes
#pragma unroll
        for (int i = 0; i < 2; i++) {
            int f   = t + i * 256;
            int row = f >> 4;            // 0..31
            int c4  = (f & 15) * 4;      // 0..60
            float4 v = *(const float4*)&W1[(kc + row) * F1 + c4];
            float4 tv;
            tv.x = __uint_as_float(f2tf(v.x));
            tv.y = __uint_as_float(f2tf(v.y));
            tv.z = __uint_as_float(f2tf(v.z));
            tv.w = __uint_as_float(f2tf(v.w));
            *(float4*)&sB[row][c4] = tv;
        }
        __syncthreads();

#pragma unroll
        for (int ks = 0; ks < 4; ks++) {
            const int k0 = ks * 8;
            uint32_t afrag[2][4];
#pragma unroll
            for (int mi = 0; mi < 2; mi++) {
                int mm = warp_m + mi * 16;
                afrag[mi][0] = __float_as_uint(sA[mm + r][k0 + c]);
                afrag[mi][1] = __float_as_uint(sA[mm + r + 8][k0 + c]);
                afrag[mi][2] = __float_as_uint(sA[mm + r][k0 + c + 4]);
                afrag[mi][3] = __float_as_uint(sA[mm + r + 8][k0 + c + 4]);
            }
            uint32_t bfrag[4][2];
#pragma unroll
            for (int ni = 0; ni < 4; ni++) {
                int nn = warp_n + ni * 8;
                bfrag[ni][0] = __float_as_uint(sB[k0 + c][nn + r]);
                bfrag[ni][1] = __float_as_uint(sB[k0 + c + 4][nn + r]);
            }
#pragma unroll
            for (int mi = 0; mi < 2; mi++)
#pragma unroll
                for (int ni = 0; ni < 4; ni++)
                    mma_tf32(acc[mi][ni], afrag[mi], bfrag[ni]);
        }
        __syncthreads();
    }

    // epilogue: store h1 + attention dots
    // thread holds rows (g, g+8), cols nn + 2c, 2c+1 of each (mi,ni) frag
#pragma unroll
    for (int mi = 0; mi < 2; mi++) {
        int row_g = m0 + warp_m + mi * 16 + r;
        int row_h = row_g + 8;
        float psg = 0.f, pdg = 0.f, psh = 0.f, pdh = 0.f;
#pragma unroll
        for (int ni = 0; ni < 4; ni++) {
            int nn = warp_n + ni * 8;
            int col = nn + c * 2;
            if (row_g < NN)
                *(float2*)&g_h1[row_g * F1 + col] = make_float2(acc[mi][ni][0], acc[mi][ni][1]);
            if (row_h < NN)
                *(float2*)&g_h1[row_h * F1 + col] = make_float2(acc[mi][ni][2], acc[mi][ni][3]);
            // attention partials (head h = nn/8, channels c*2, c*2+1)
            float as0 = sAs[col], as1v = sAs[col + 1];
            float ad0 = sAd[col], ad1v = sAd[col + 1];
            psg = acc[mi][ni][0] * as0 + acc[mi][ni][1] * as1v;
            pdg = acc[mi][ni][0] * ad0 + acc[mi][ni][1] * ad1v;
            psh = acc[mi][ni][2] * as0 + acc[mi][ni][3] * as1v;
            pdh = acc[mi][ni][2] * ad0 + acc[mi][ni][3] * ad1v;
#pragma unroll
            for (int off = 1; off <= 2; off <<= 1) {
                psg += __shfl_xor_sync(FULLM, psg, off);
                pdg += __shfl_xor_sync(FULLM, pdg, off);
                psh += __shfl_xor_sync(FULLM, psh, off);
                pdh += __shfl_xor_sync(FULLM, pdh, off);
            }
            int h = nn >> 3;
            if (c == 0) {
                if (row_g < NN) { g_as1[row_g * NH1 + h] = psg; g_ad1[row_g * NH1 + h] = pdg; }
                if (row_h < NN) { g_as1[row_h * NH1 + h] = psh; g_ad1[row_h * NH1 + h] = pdh; }
            }
        }
    }
}

// ------------------------- CSR build
__global__ void k_zero() {
    int i = blockIdx.x * blockDim.x + threadIdx.x;
    if (i < NN) g_deg[i] = 0;
}
__global__ void k_hist(const int* __restrict__ dst) {
    int e = blockIdx.x * blockDim.x + threadIdx.x;
    if (e < EE) atomicAdd(&g_deg[dst[e]], 1);
}
__global__ __launch_bounds__(256) void k_part() {
    __shared__ int sm[256];
    int t = threadIdx.x, i = blockIdx.x * 256 + t;
    int d = (i < NN) ? g_deg[i] : 0;
    sm[t] = d;
    __syncthreads();
#pragma unroll
    for (int off = 1; off < 256; off <<= 1) {
        int v = (t >= off) ? sm[t - off] : 0;
        __syncthreads();
        sm[t] += v;
        __syncthreads();
    }
    if (i < NN) g_rowloc[i] = sm[t] - d;
    if (t == 255) g_bsum[blockIdx.x] = sm[255];
}
__global__ __launch_bounds__(256) void k_bscan() {
    __shared__ int sm[256];
    int t = threadIdx.x;
    int d = (t < NBLK) ? g_bsum[t] : 0;
    sm[t] = d;
    __syncthreads();
#pragma unroll
    for (int off = 1; off < 256; off <<= 1) {
        int v = (t >= off) ? sm[t - off] : 0;
        __syncthreads();
        sm[t] += v;
        __syncthreads();
    }
    if (t < NBLK) g_boff[t] = sm[t] - d;
    if (t == NBLK - 1) g_rowptr[NN] = sm[t];
}
__global__ void k_fix() {
    int i = blockIdx.x * blockDim.x + threadIdx.x;
    if (i < NN) {
        int rp = g_rowloc[i] + g_boff[blockIdx.x];
        g_rowptr[i] = rp;
        g_cursor[i] = rp;
    }
}
__global__ void k_scatter(const int* __restrict__ src, const int* __restrict__ dst) {
    int e = blockIdx.x * blockDim.x + threadIdx.x;
    if (e < EE) {
        int d = dst[e];
        int p = atomicAdd(&g_cursor[d], 1);
        g_col[p] = src[e];
    }
}

// ------------------------- layer-1 aggregation + fused layer-2 linear/att
// one warp per dst node; no max pass (logits are tiny; softmax shift-invariant)
__global__ __launch_bounds__(256) void k_agg1(const float* __restrict__ b1,
                                              const float* __restrict__ W2,
                                              const float* __restrict__ att_s,
                                              const float* __restrict__ att_d) {
    __shared__ float swt[8][8][36];
    __shared__ int   ssrc[8][32];
    __shared__ float sW2[F1 * C2];
    __shared__ float sAs2[C2], sAd2[C2];

    for (int idx = threadIdx.x; idx < F1 * C2; idx += 256) sW2[idx] = W2[idx];
    if (threadIdx.x < C2) {
        sAs2[threadIdx.x] = att_s[threadIdx.x];
        sAd2[threadIdx.x] = att_d[threadIdx.x];
    }
    __syncthreads();

    const int w    = threadIdx.x >> 5;
    const int lane = threadIdx.x & 31;
    const int node = blockIdx.x * 8 + w;
    if (node >= NN) return;
    const int beg   = g_rowptr[node];
    const int deg   = g_rowptr[node + 1] - beg;
    const int total = deg + 1;

    float4 ad0 = *(const float4*)&g_ad1[node * 8];
    float4 ad1 = *(const float4*)&g_ad1[node * 8 + 4];
    float adr[8] = { ad0.x, ad0.y, ad0.z, ad0.w, ad1.x, ad1.y, ad1.z, ad1.w };

    const int hl = lane >> 2;
    const int c0 = lane * 2;
    float acc0 = 0.f, acc1 = 0.f;
    float ssum[8];
#pragma unroll
    for (int h = 0; h < 8; h++) ssum[h] = 0.f;

    for (int k0 = 0; k0 < total; k0 += 32) {
        int kk  = k0 + lane;
        int lim = min(32, total - k0);
        __syncwarp();
        if (kk < total) {
            int srcn = (kk < deg) ? g_col[beg + kk] : node;
            float4 s0 = *(const float4*)&g_as1[srcn * 8];
            float4 s1 = *(const float4*)&g_as1[srcn * 8 + 4];
            float lg[8] = { s0.x + adr[0], s0.y + adr[1], s0.z + adr[2], s0.w + adr[3],
                            s1.x + adr[4], s1.y + adr[5], s1.z + adr[6], s1.w + adr[7] };
#pragma unroll
            for (int h = 0; h < 8; h++) {
                float wt = __expf(leaky(lg[h]));
                ssum[h] += wt;
                swt[w][h][lane] = wt;
            }
            ssrc[w][lane] = srcn;
        }
        __syncwarp();
        for (int j = 0; j < lim; j++) {
            int srcn = ssrc[w][j];
            float wt = swt[w][hl][j];
            float2 hv = *(const float2*)&g_h1[srcn * F1 + c0];
            acc0 += wt * hv.x;
            acc1 += wt * hv.y;
        }
    }
#pragma unroll
    for (int h = 0; h < 8; h++) {
#pragma unroll
        for (int off = 16; off > 0; off >>= 1)
            ssum[h] += __shfl_xor_sync(FULLM, ssum[h], off);
    }
    float myS = 0.f;
#pragma unroll
    for (int h = 0; h < 8; h++)
        if (hl == h) myS = ssum[h];
    float inv = __fdividef(1.0f, myS);

    // x2 row in registers (relu + bias)
    float v0 = fmaxf(acc0 * inv + b1[c0], 0.f);
    float v1 = fmaxf(acc1 * inv + b1[c0 + 1], 0.f);

    // fused layer-2 linear: h2 = x2 @ W2  (+ attention coefficients)
    const int cA = lane;
    const int cB = lane + 32;
    const bool has1 = (lane < 8);
    float a0 = 0.f, a1 = 0.f;
#pragma unroll
    for (int kk = 0; kk < 32; kk++) {
        float x0 = __shfl_sync(FULLM, v0, kk);
        float x1 = __shfl_sync(FULLM, v1, kk);
        a0 += x0 * sW2[(2 * kk) * C2 + cA] + x1 * sW2[(2 * kk + 1) * C2 + cA];
        if (has1)
            a1 += x0 * sW2[(2 * kk) * C2 + cB] + x1 * sW2[(2 * kk + 1) * C2 + cB];
    }
    g_h2[node * C2 + cA] = a0;
    if (has1) g_h2[node * C2 + cB] = a1;

    float ps = a0 * sAs2[cA] + (has1 ? a1 * sAs2[cB] : 0.f);
    float pd = a0 * sAd2[cA] + (has1 ? a1 * sAd2[cB] : 0.f);
#pragma unroll
    for (int off = 16; off > 0; off >>= 1) {
        ps += __shfl_xor_sync(FULLM, ps, off);
        pd += __shfl_xor_sync(FULLM, pd, off);
    }
    if (lane == 0) { g_as2[node] = ps; g_ad2[node] = pd; }
}

// ------------------------- layer-2 aggregation + bias + log_softmax (warp/node)
__global__ __launch_bounds__(256) void k_agg2(const float* __restrict__ b2,
                                              float* __restrict__ out) {
    __shared__ float swt[8][32];
    __shared__ int   ssrc[8][32];
    const int w    = threadIdx.x >> 5;
    const int lane = threadIdx.x & 31;
    const int node = blockIdx.x * 8 + w;
    if (node >= NN) return;
    const int beg   = g_rowptr[node];
    const int deg   = g_rowptr[node + 1] - beg;
    const int total = deg + 1;
    const float adn = g_ad2[node];

    const int c0 = lane;
    const int c1 = lane + 32;
    const bool has1 = (c1 < C2);
    float acc0 = 0.f, acc1 = 0.f, ssum = 0.f;
    for (int k0 = 0; k0 < total; k0 += 32) {
        int kk  = k0 + lane;
        int lim = min(32, total - k0);
        __syncwarp();
        if (kk < total) {
            int srcn = (kk < deg) ? g_col[beg + kk] : node;
            float wt = __expf(leaky(g_as2[srcn] + adn));
            ssum += wt;
            swt[w][lane]  = wt;
            ssrc[w][lane] = srcn;
        }
        __syncwarp();
        for (int j = 0; j < lim; j++) {
            int srcn = ssrc[w][j];
            float wt = swt[w][j];
            acc0 += wt * g_h2[srcn * C2 + c0];
            if (has1) acc1 += wt * g_h2[srcn * C2 + c1];
        }
    }
#pragma unroll
    for (int off = 16; off > 0; off >>= 1)
        ssum += __shfl_xor_sync(FULLM, ssum, off);
    float inv = __fdividef(1.0f, ssum);

    float o0 = acc0 * inv + b2[c0];
    float o1 = has1 ? (acc1 * inv + b2[c1]) : -1e30f;

    float mx = fmaxf(o0, o1);
#pragma unroll
    for (int off = 16; off > 0; off >>= 1)
        mx = fmaxf(mx, __shfl_xor_sync(FULLM, mx, off));
    float se = __expf(o0 - mx) + (has1 ? __expf(o1 - mx) : 0.f);
#pragma unroll
    for (int off = 16; off > 0; off >>= 1)
        se += __shfl_xor_sync(FULLM, se, off);
    float lse = mx + __logf(se);

    out[node * C2 + c0] = o0 - lse;
    if (has1) out[node * C2 + c1] = o1 - lse;
}

// ------------------------- launch
extern "C" void kernel_launch(void* const* d_in, const int* in_sizes, int n_in,
                              void* d_out, int out_size) {
    const float* x        = (const float*)d_in[0];
    const int*   ei       = (const int*)d_in[1];
    const float* W1       = (const float*)d_in[2];
    const float* att_src1 = (const float*)d_in[3];
    const float* att_dst1 = (const float*)d_in[4];
    const float* b1       = (const float*)d_in[5];
    const float* W2       = (const float*)d_in[6];
    const float* att_src2 = (const float*)d_in[7];
    const float* att_dst2 = (const float*)d_in[8];
    const float* b2       = (const float*)d_in[9];
    float* out = (float*)d_out;

    const int* src = ei;
    const int* dst = ei + EE;

    // CSR build
    k_zero<<<(NN + 255) / 256, 256>>>();
    k_hist<<<(EE + 255) / 256, 256>>>(dst);
    k_part<<<NBLK, 256>>>();
    k_bscan<<<1, 256>>>();
    k_fix<<<NBLK, 256>>>();
    k_scatter<<<(EE + 255) / 256, 256>>>(src, dst);

    // layer 1 (tf32 tensor-core GEMM + fused att coeffs)
    k_gemm1<<<(NN + 127) / 128, 256>>>(x, W1, att_src1, att_dst1);

    // layer-1 aggregation fused with layer-2 linear + att coeffs
    k_agg1<<<(NN + 7) / 8, 256>>>(b1, W2, att_src2, att_dst2);

    // layer-2 aggregation + log_softmax
    k_agg2<<<(NN + 7) / 8, 256>>>(b2, out);
}